// round 12
// baseline (speedup 1.0000x reference)
#include <cuda_runtime.h>
#include <cuda_bf16.h>
#include <cuda_fp16.h>
#include <cstdint>

// Problem dims
#define BB 2
#define TT 1024
#define VV 2048
#define DD 1024
#define HH 16
#define LL 8
#define DK 64
#define FF 4096
#define MROWS (BB*TT)   // 2048

typedef __half f16;

// ---------------- static scratch (no allocations allowed) ----------------
__device__ float g_x   [MROWS * DD];        // residual stream (fp32)
__device__ float g_qkv [MROWS * 3 * DD];    // fused qkv activations (fp32)
__device__ float g_bqkv[LL * 3 * DD];       // fused qkv bias

// fp16 split planes: activations (A side: hi+lo)
__device__ __align__(128) f16 g_hhi [MROWS * DD];
__device__ __align__(128) f16 g_hlo [MROWS * DD];
__device__ __align__(128) f16 g_athi[MROWS * DD];
__device__ __align__(128) f16 g_atlo[MROWS * DD];
__device__ __align__(128) f16 g_ffhi[MROWS * FF];
__device__ __align__(128) f16 g_fflo[MROWS * FF];
__device__ __align__(128) f16 g_ixhi[MROWS * VV];
__device__ __align__(128) f16 g_ixlo[MROWS * VV];

// fp16 single-plane weights, transposed to [N,K]
#define OFF_TOK  0ull
#define OFF_QKV  2097152ull
#define OFF_PROJ 27262976ull
#define OFF_FF1  35651584ull
#define OFF_FF2  69206016ull
#define OFF_HEAD 102760448ull
#define W_TOTAL  104857600ull
__device__ __align__(128) f16 g_w[W_TOTAL];

// ---------------- small helpers ----------------
__device__ __forceinline__ uint32_t smem_u32(const void* p) {
    uint32_t a;
    asm("{ .reg .u64 t; cvta.to.shared.u64 t, %1; cvt.u32.u64 %0, t; }" : "=r"(a) : "l"(p));
    return a;
}
__device__ __forceinline__ void split_store(f16* hi, f16* lo, size_t idx, float v) {
    f16 h = __float2half(v);
    hi[idx] = h;
    lo[idx] = __float2half(v - __half2float(h));
}
__device__ __forceinline__ void ldsm4(uint32_t& r0, uint32_t& r1, uint32_t& r2, uint32_t& r3,
                                      uint32_t addr) {
    asm volatile("ldmatrix.sync.aligned.m8n8.x4.shared.b16 {%0,%1,%2,%3}, [%4];"
                 : "=r"(r0), "=r"(r1), "=r"(r2), "=r"(r3) : "r"(addr));
}
__device__ __forceinline__ void mma16816(float* d, const uint32_t* a, const uint32_t* b) {
    asm volatile(
        "mma.sync.aligned.m16n8k16.row.col.f32.f16.f16.f32 "
        "{%0,%1,%2,%3}, {%4,%5,%6,%7}, {%8,%9}, {%0,%1,%2,%3};"
        : "+f"(d[0]), "+f"(d[1]), "+f"(d[2]), "+f"(d[3])
        : "r"(a[0]), "r"(a[1]), "r"(a[2]), "r"(a[3]), "r"(b[0]), "r"(b[1]));
}
// fp16-accumulator variant (tests the 2x-rate hypothesis for the lo pass)
__device__ __forceinline__ void mma16816h(uint32_t* d, const uint32_t* a, const uint32_t* b) {
    asm volatile(
        "mma.sync.aligned.m16n8k16.row.col.f16.f16.f16.f16 "
        "{%0,%1}, {%2,%3,%4,%5}, {%6,%7}, {%0,%1};"
        : "+r"(d[0]), "+r"(d[1])
        : "r"(a[0]), "r"(a[1]), "r"(a[2]), "r"(a[3]), "r"(b[0]), "r"(b[1]));
}

// ---------------- weight prep: transpose + fp16 (single plane) ----------------
__global__ void tsplit_kernel(const float* __restrict__ src, f16* __restrict__ dst,
                              int K, int N, long sStride, long dStride) {
    int z = blockIdx.z;
    src += (size_t)z * sStride;
    dst += (size_t)z * dStride;
    __shared__ float t[32][33];
    int n0 = blockIdx.x * 32, k0 = blockIdx.y * 32;
    int tx = threadIdx.x, ty = threadIdx.y;
#pragma unroll
    for (int i = 0; i < 4; i++)
        t[ty + 8 * i][tx] = src[(size_t)(k0 + ty + 8 * i) * N + n0 + tx];
    __syncthreads();
#pragma unroll
    for (int i = 0; i < 4; i++) {
        int n = n0 + ty + 8 * i, k = k0 + tx;
        dst[(size_t)n * K + k] = __float2half(t[tx][ty + 8 * i]);
    }
}

// wq/wk/wv [L,H,D,DK] -> fused [3072,1024] per layer (transposed, fp16)
__global__ void tsplit_qkv(const float* __restrict__ wq, const float* __restrict__ wk,
                           const float* __restrict__ wv, f16* __restrict__ dst) {
    int z = blockIdx.z;                       // seg*L*H + l*H + h
    int seg = z / (LL * HH);
    int r = z % (LL * HH);
    int l = r / HH, h = r % HH;
    const float* src = (seg == 0 ? wq : seg == 1 ? wk : wv) + (size_t)(l * HH + h) * DD * DK;
    size_t dbase = (size_t)l * (3 * DD) * DD + (size_t)seg * DD * DD + (size_t)h * DK * DD;
    __shared__ float t[32][33];
    int n0 = blockIdx.x * 32, k0 = blockIdx.y * 32;
    int tx = threadIdx.x, ty = threadIdx.y;
#pragma unroll
    for (int i = 0; i < 4; i++)
        t[ty + 8 * i][tx] = src[(size_t)(k0 + ty + 8 * i) * DK + n0 + tx];
    __syncthreads();
#pragma unroll
    for (int i = 0; i < 4; i++) {
        int n = n0 + ty + 8 * i, k = k0 + tx;
        dst[dbase + (size_t)n * DD + k] = __float2half(t[tx][ty + 8 * i]);
    }
}

__global__ void prep_bqkv(const float* __restrict__ bq, const float* __restrict__ bk,
                          const float* __restrict__ bv, float* __restrict__ bt) {
    int idx = blockIdx.x * 256 + threadIdx.x;
    if (idx >= LL * 3 * DD) return;
    int c = idx % (3 * DD);
    int l = idx / (3 * DD);
    int seg = c >> 10;
    int hk = c & 1023;
    int h = hk >> 6, k = hk & 63;
    const float* src = (seg == 0) ? bq : (seg == 1 ? bk : bv);
    bt[idx] = src[(l * HH + h) * DK + k];
}

// elementwise fp32 -> hi/lo fp16 (for idx input)
__global__ void split_kernel(const float* __restrict__ src, f16* __restrict__ hi,
                             f16* __restrict__ lo, int n) {
    int i = blockIdx.x * 256 + threadIdx.x;
    if (i < n) split_store(hi, lo, i, src[i]);
}

// ---------------- LayerNorm: outputs fp16 hi/lo planes ----------------
__global__ void ln_kernel(const float* __restrict__ in, f16* __restrict__ ohi,
                          f16* __restrict__ olo, const float* __restrict__ g,
                          const float* __restrict__ b) {
    int row = blockIdx.x;
    int tid = threadIdx.x;
    const float* p = in + (size_t)row * DD;
    float v[4];
#pragma unroll
    for (int i = 0; i < 4; i++) v[i] = p[tid + i * 256];
    __shared__ float red[256];
    red[tid] = v[0] + v[1] + v[2] + v[3];
    __syncthreads();
#pragma unroll
    for (int off = 128; off > 0; off >>= 1) {
        if (tid < off) red[tid] += red[tid + off];
        __syncthreads();
    }
    float mean = red[0] * (1.0f / DD);
    __syncthreads();
    float s2 = 0.f;
#pragma unroll
    for (int i = 0; i < 4; i++) { float d = v[i] - mean; s2 += d * d; }
    red[tid] = s2;
    __syncthreads();
#pragma unroll
    for (int off = 128; off > 0; off >>= 1) {
        if (tid < off) red[tid] += red[tid + off];
        __syncthreads();
    }
    float r = rsqrtf(red[0] * (1.0f / DD) + 1e-5f);
#pragma unroll
    for (int i = 0; i < 4; i++) {
        int col = tid + i * 256;
        float val = (v[i] - mean) * r * g[col] + b[col];
        split_store(ohi, olo, (size_t)row * DD + col, val);
    }
}

// ---------------- split-fp16 HMMA GEMM (2-pass, mixed accumulators) ----------------
// C[M,N] = A[M,K] * W[K,N]; A as fp16 hi/lo planes [M,K], W single fp16 plane [N,K].
// Pass 0 (Ahi*W): fp32 accumulators. Pass 1 (Alo*W): fp16 accumulators — the lo
// term is ~2^-11 of C so fp16 accumulation error is ~8e-6 of C; if the legacy
// HMMA pipe runs f16-accum at 2x the f32-accum rate this pass becomes half-cost.
// Block tile 128x128, BK=32, 256 threads, 8 warps of 64x32.
// 3-stage cp.async pipeline, one __syncthreads per K-chunk. Stage = 24KB.
// EPI: 0 = fp32 +bias ; 1 = fp32 +bias+pos ; 2 = fp32 +bias+extra ; 3 = fp16 relu split
#define STG 24576
#define SMEM_MM (3 * STG)

template <int EPI>
__global__ __launch_bounds__(256) void mm_kernel(
    const f16* __restrict__ Ahi, const f16* __restrict__ Alo,
    const f16* __restrict__ Bw,
    float* __restrict__ C, const float* __restrict__ bias,
    const float* __restrict__ extra, f16* __restrict__ Ohi, f16* __restrict__ Olo,
    int N, int K) {
    extern __shared__ __align__(128) char smem[];
    uint32_t sb = smem_u32(smem);
    int tid = threadIdx.x, lane = tid & 31, wid = tid >> 5;
    int wm = wid >> 2, wn = wid & 3;            // warp grid 2x4, warp tile 64x32
    const int mBase = blockIdx.y * 128, nBase = blockIdx.x * 128;
    const f16* srcs[3] = { Ahi + (size_t)mBase * K, Alo + (size_t)mBase * K,
                           Bw + (size_t)nBase * K };
    const int NC = K >> 5;

    float acc[4][4][4];
    uint32_t acch[4][4][2];
#pragma unroll
    for (int i = 0; i < 4; i++)
#pragma unroll
        for (int j = 0; j < 4; j++) {
#pragma unroll
            for (int c = 0; c < 4; c++) acc[i][j][c] = 0.f;
            acch[i][j][0] = 0u; acch[i][j][1] = 0u;
        }

    int rowh = tid >> 2;     // 0..63
    int ch = tid & 3;        // 16B chunk within 64B row

    auto issue = [&](int c, int s) {
#pragma unroll
        for (int p = 0; p < 3; p++) {
#pragma unroll
            for (int w = 0; w < 2; w++) {
                int row = rowh + w * 64;
                int cc = ch ^ ((row >> 1) & 3);
                uint32_t d = sb + s * STG + p * 8192 + row * 64 + cc * 16;
                const f16* g = srcs[p] + (size_t)row * K + c * 32 + ch * 8;
                asm volatile("cp.async.cg.shared.global [%0], [%1], 16;"
                             :: "r"(d), "l"(g) : "memory");
            }
        }
        asm volatile("cp.async.commit_group;" ::: "memory");
    };

    // per-lane ldmatrix constants
    int mrl = ((lane >> 3) & 1) * 8 + (lane & 7);   // A: local m row
    int kha = (lane >> 4) & 1;                      // A: k half
    int nrl = ((lane >> 4) & 1) * 8 + (lane & 7);   // B: local n row
    int khb = (lane >> 3) & 1;                      // B: k half
    uint32_t aRow[4], aSw[4], bRow[2], bSw[2];
#pragma unroll
    for (int mt = 0; mt < 4; mt++) {
        int row = wm * 64 + mt * 16 + mrl;
        aRow[mt] = row * 64;
        aSw[mt] = (row >> 1) & 3;
    }
#pragma unroll
    for (int p2 = 0; p2 < 2; p2++) {
        int row = wn * 32 + p2 * 16 + nrl;
        bRow[p2] = row * 64;
        bSw[p2] = (row >> 1) & 3;
    }

    issue(0, 0);
    if (NC > 1) issue(1, 1);

    for (int r = 0; r < NC; r++) {
        if (r + 1 < NC) {
            asm volatile("cp.async.wait_group 1;" ::: "memory");
        } else {
            asm volatile("cp.async.wait_group 0;" ::: "memory");
        }
        __syncthreads();   // publishes chunk r AND guards stage (r-1) reuse
        if (r + 2 < NC) issue(r + 2, (r + 2) % 3);
        uint32_t stage = sb + (r % 3) * STG;
#pragma unroll
        for (int pass = 0; pass < 2; pass++) {
            uint32_t aOff = stage + (pass == 1 ? 8192 : 0);   // Ahi / Alo
            uint32_t bOff = stage + 16384;                    // B (shared by both passes)
#pragma unroll
            for (int ks = 0; ks < 2; ks++) {
                uint32_t a[4][4];
#pragma unroll
                for (int mt = 0; mt < 4; mt++) {
                    uint32_t cc = (uint32_t)(ks * 2 + kha) ^ aSw[mt];
                    ldsm4(a[mt][0], a[mt][1], a[mt][2], a[mt][3],
                          aOff + aRow[mt] + cc * 16);
                }
                uint32_t bb[8];
#pragma unroll
                for (int p2 = 0; p2 < 2; p2++) {
                    uint32_t cc = (uint32_t)(ks * 2 + khb) ^ bSw[p2];
                    ldsm4(bb[p2 * 4], bb[p2 * 4 + 1], bb[p2 * 4 + 2], bb[p2 * 4 + 3],
                          bOff + bRow[p2] + cc * 16);
                }
                if (pass == 0) {
#pragma unroll
                    for (int mt = 0; mt < 4; mt++)
#pragma unroll
                        for (int nt = 0; nt < 4; nt++)
                            mma16816(acc[mt][nt], a[mt], &bb[nt * 2]);
                } else {
#pragma unroll
                    for (int mt = 0; mt < 4; mt++)
#pragma unroll
                        for (int nt = 0; nt < 4; nt++)
                            mma16816h(acch[mt][nt], a[mt], &bb[nt * 2]);
                }
            }
        }
    }

    // merge fp16 lo-pass accumulators into fp32
#pragma unroll
    for (int mt = 0; mt < 4; mt++)
#pragma unroll
        for (int nt = 0; nt < 4; nt++) {
            float2 f0 = __half22float2(*(const __half2*)&acch[mt][nt][0]);
            float2 f1 = __half22float2(*(const __half2*)&acch[mt][nt][1]);
            acc[mt][nt][0] += f0.x; acc[mt][nt][1] += f0.y;
            acc[mt][nt][2] += f1.x; acc[mt][nt][3] += f1.y;
        }

    // epilogue: direct global writes
#pragma unroll
    for (int mt = 0; mt < 4; mt++) {
#pragma unroll
        for (int nt = 0; nt < 4; nt++) {
            int m0 = mBase + wm * 64 + mt * 16 + (lane >> 2);
            int n0 = nBase + wn * 32 + nt * 8 + (lane & 3) * 2;
            float b0 = bias[n0], b1 = bias[n0 + 1];
            float v00 = acc[mt][nt][0] + b0, v01 = acc[mt][nt][1] + b1;
            float v10 = acc[mt][nt][2] + b0, v11 = acc[mt][nt][3] + b1;
            int m1 = m0 + 8;
            if (EPI == 1) {
                v00 += extra[(size_t)(m0 & (TT - 1)) * N + n0];
                v01 += extra[(size_t)(m0 & (TT - 1)) * N + n0 + 1];
                v10 += extra[(size_t)(m1 & (TT - 1)) * N + n0];
                v11 += extra[(size_t)(m1 & (TT - 1)) * N + n0 + 1];
            }
            if (EPI == 2) {
                v00 += extra[(size_t)m0 * N + n0];
                v01 += extra[(size_t)m0 * N + n0 + 1];
                v10 += extra[(size_t)m1 * N + n0];
                v11 += extra[(size_t)m1 * N + n0 + 1];
            }
            if (EPI == 3) {
                v00 = fmaxf(v00, 0.f); v01 = fmaxf(v01, 0.f);
                v10 = fmaxf(v10, 0.f); v11 = fmaxf(v11, 0.f);
                split_store(Ohi, Olo, (size_t)m0 * N + n0, v00);
                split_store(Ohi, Olo, (size_t)m0 * N + n0 + 1, v01);
                split_store(Ohi, Olo, (size_t)m1 * N + n0, v10);
                split_store(Ohi, Olo, (size_t)m1 * N + n0 + 1, v11);
            } else {
                float2 lo2 = { v00, v01 };
                float2 hi2 = { v10, v11 };
                *(float2*)&C[(size_t)m0 * N + n0] = lo2;
                *(float2*)&C[(size_t)m1 * N + n0] = hi2;
            }
        }
    }
}

// ---------------- fused causal attention (flash-style, fp32 in, fp16 split out) ----------
__global__ __launch_bounds__(64) void attn_kernel(const float* __restrict__ qkv,
                                                  f16* __restrict__ ohi,
                                                  f16* __restrict__ olo) {
    __shared__ float buf[64 * 64];
    __shared__ float Sc[64 * 65];
    int tid = threadIdx.x;
    int t0 = blockIdx.x * 64;
    int h = blockIdx.y;
    int b = blockIdx.z;
    int t = t0 + tid;

    const float4* qrow = (const float4*)(qkv + (size_t)(b * TT + t) * (3 * DD) + h * DK);
    float q[64], o[64];
#pragma unroll
    for (int i = 0; i < 16; i++) ((float4*)q)[i] = qrow[i];
#pragma unroll
    for (int j = 0; j < 64; j++) o[j] = 0.f;
    float mrow = -1e30f, lrow = 0.f;

    for (int s0 = 0; s0 <= t0; s0 += 64) {
        __syncthreads();
        {
            const float4* kb = (const float4*)(qkv + (size_t)(b * TT + s0 + tid) * (3 * DD)
                                               + DD + h * DK);
            float4* dst = (float4*)&buf[tid * 64];
#pragma unroll
            for (int i = 0; i < 16; i++) dst[i] = kb[i];
        }
        __syncthreads();
        float tmax = -1e30f;
        bool diag = (s0 == t0);
        for (int s = 0; s < 64; s++) {
            float acc = 0.f;
#pragma unroll
            for (int j = 0; j < 64; j++) acc += q[j] * buf[s * 64 + j];
            acc *= 0.125f;
            if (diag && s > tid) acc = -1e30f;
            Sc[tid * 65 + s] = acc;
            tmax = fmaxf(tmax, acc);
        }
        __syncthreads();
        {
            const float4* vb = (const float4*)(qkv + (size_t)(b * TT + s0 + tid) * (3 * DD)
                                               + 2 * DD + h * DK);
            float4* dst = (float4*)&buf[tid * 64];
#pragma unroll
            for (int i = 0; i < 16; i++) dst[i] = vb[i];
        }
        __syncthreads();
        float mnew = fmaxf(mrow, tmax);
        float corr = __expf(mrow - mnew);
        lrow *= corr;
#pragma unroll
        for (int j = 0; j < 64; j++) o[j] *= corr;
        for (int s = 0; s < 64; s++) {
            float p = __expf(Sc[tid * 65 + s] - mnew);
            lrow += p;
#pragma unroll
            for (int j = 0; j < 64; j++) o[j] += p * buf[s * 64 + j];
        }
        mrow = mnew;
    }
    float inv = 1.f / lrow;
    size_t obase = (size_t)(b * TT + t) * DD + h * DK;
#pragma unroll
    for (int j = 0; j < 64; j++) split_store(ohi, olo, obase + j, o[j] * inv);
}

// ---------------- host orchestration ----------------
extern "C" void kernel_launch(void* const* d_in, const int* in_sizes, int n_in,
                              void* d_out, int out_size) {
    const float* idx    = (const float*)d_in[0];
    const float* tok_w  = (const float*)d_in[1];
    const float* tok_b  = (const float*)d_in[2];
    const float* pos    = (const float*)d_in[3];
    const float* ln1_g  = (const float*)d_in[4];
    const float* ln1_b  = (const float*)d_in[5];
    const float* wq     = (const float*)d_in[6];
    const float* wk     = (const float*)d_in[7];
    const float* wv     = (const float*)d_in[8];
    const float* bq     = (const float*)d_in[9];
    const float* bk     = (const float*)d_in[10];
    const float* bv     = (const float*)d_in[11];
    const float* proj_w = (const float*)d_in[12];
    const float* proj_b = (const float*)d_in[13];
    const float* ln2_g  = (const float*)d_in[14];
    const float* ln2_b  = (const float*)d_in[15];
    const float* ff1_w  = (const float*)d_in[16];
    const float* ff1_b  = (const float*)d_in[17];
    const float* ff2_w  = (const float*)d_in[18];
    const float* ff2_b  = (const float*)d_in[19];
    const float* lnf_g  = (const float*)d_in[20];
    const float* lnf_b  = (const float*)d_in[21];
    const float* head_w = (const float*)d_in[22];
    const float* head_b = (const float*)d_in[23];
    float* out = (float*)d_out;

    float *x, *qkv, *bqkv;
    f16 *hhi, *hlo, *athi, *atlo, *ffhi, *fflo, *ixhi, *ixlo, *w;
    cudaGetSymbolAddress((void**)&x, g_x);
    cudaGetSymbolAddress((void**)&qkv, g_qkv);
    cudaGetSymbolAddress((void**)&bqkv, g_bqkv);
    cudaGetSymbolAddress((void**)&hhi, g_hhi);
    cudaGetSymbolAddress((void**)&hlo, g_hlo);
    cudaGetSymbolAddress((void**)&athi, g_athi);
    cudaGetSymbolAddress((void**)&atlo, g_atlo);
    cudaGetSymbolAddress((void**)&ffhi, g_ffhi);
    cudaGetSymbolAddress((void**)&fflo, g_fflo);
    cudaGetSymbolAddress((void**)&ixhi, g_ixhi);
    cudaGetSymbolAddress((void**)&ixlo, g_ixlo);
    cudaGetSymbolAddress((void**)&w, g_w);

    cudaFuncSetAttribute(mm_kernel<0>, cudaFuncAttributeMaxDynamicSharedMemorySize, SMEM_MM);
    cudaFuncSetAttribute(mm_kernel<1>, cudaFuncAttributeMaxDynamicSharedMemorySize, SMEM_MM);
    cudaFuncSetAttribute(mm_kernel<2>, cudaFuncAttributeMaxDynamicSharedMemorySize, SMEM_MM);
    cudaFuncSetAttribute(mm_kernel<3>, cudaFuncAttributeMaxDynamicSharedMemorySize, SMEM_MM);

    dim3 tb(32, 8);
    // weight prep: transpose + fp16 convert (single plane)
    tsplit_kernel<<<dim3(32, 64, 1), tb>>>(tok_w, w + OFF_TOK, 2048, 1024, 0, 0);
    tsplit_qkv<<<dim3(2, 32, 3 * LL * HH), tb>>>(wq, wk, wv, w + OFF_QKV);
    prep_bqkv<<<(LL * 3 * DD + 255) / 256, 256>>>(bq, bk, bv, bqkv);
    tsplit_kernel<<<dim3(32, 32, LL), tb>>>(proj_w, w + OFF_PROJ, 1024, 1024,
                                            1048576, 1048576);
    tsplit_kernel<<<dim3(128, 32, LL), tb>>>(ff1_w, w + OFF_FF1, 1024, 4096,
                                             4194304, 4194304);
    tsplit_kernel<<<dim3(32, 128, LL), tb>>>(ff2_w, w + OFF_FF2, 4096, 1024,
                                             4194304, 4194304);
    tsplit_kernel<<<dim3(64, 32, 1), tb>>>(head_w, w + OFF_HEAD, 1024, 2048, 0, 0);
    split_kernel<<<(MROWS * VV + 255) / 256, 256>>>(idx, ixhi, ixlo, MROWS * VV);

    // embedding: x = idx @ tok_w + tok_b + pos
    mm_kernel<1><<<dim3(8, 16), 256, SMEM_MM>>>(
        ixhi, ixlo, w + OFF_TOK, x, tok_b, pos, nullptr, nullptr, DD, VV);

    for (int l = 0; l < LL; l++) {
        ln_kernel<<<MROWS, 256>>>(x, hhi, hlo, ln1_g + l * DD, ln1_b + l * DD);
        mm_kernel<0><<<dim3(24, 16), 256, SMEM_MM>>>(
            hhi, hlo, w + OFF_QKV + (size_t)l * 3145728,
            qkv, bqkv + l * 3 * DD, nullptr, nullptr, nullptr, 3 * DD, DD);
        attn_kernel<<<dim3(TT / 64, HH, BB), 64>>>(qkv, athi, atlo);
        mm_kernel<2><<<dim3(8, 16), 256, SMEM_MM>>>(
            athi, atlo, w + OFF_PROJ + (size_t)l * 1048576,
            x, proj_b + l * DD, x, nullptr, nullptr, DD, DD);
        ln_kernel<<<MROWS, 256>>>(x, hhi, hlo, ln2_g + l * DD, ln2_b + l * DD);
        mm_kernel<3><<<dim3(32, 16), 256, SMEM_MM>>>(
            hhi, hlo, w + OFF_FF1 + (size_t)l * 4194304,
            nullptr, ff1_b + l * FF, nullptr, ffhi, fflo, FF, DD);
        mm_kernel<2><<<dim3(8, 16), 256, SMEM_MM>>>(
            ffhi, fflo, w + OFF_FF2 + (size_t)l * 4194304,
            x, ff2_b + l * DD, x, nullptr, nullptr, DD, FF);
    }

    ln_kernel<<<MROWS, 256>>>(x, hhi, hlo, lnf_g, lnf_b);
    mm_kernel<0><<<dim3(16, 16), 256, SMEM_MM>>>(
        hhi, hlo, w + OFF_HEAD, out, head_b, nullptr, nullptr, nullptr, VV, DD);
}

// round 14
// speedup vs baseline: 1.1151x; 1.1151x over previous
#include <cuda_runtime.h>
#include <cuda_bf16.h>
#include <cuda_fp16.h>
#include <cstdint>

// Problem dims
#define BB 2
#define TT 1024
#define VV 2048
#define DD 1024
#define HH 16
#define LL 8
#define DK 64
#define FF 4096
#define MROWS (BB*TT)   // 2048

typedef __half f16;

// ---------------- static scratch (no allocations allowed) ----------------
__device__ float g_x   [MROWS * DD];        // residual stream (fp32)
__device__ float g_qkv [MROWS * 3 * DD];    // fused qkv activations (fp32)
__device__ float g_bqkv[LL * 3 * DD];       // fused qkv bias

// fp16 split planes: activations (A side: hi+lo)
__device__ __align__(128) f16 g_hhi [MROWS * DD];
__device__ __align__(128) f16 g_hlo [MROWS * DD];
__device__ __align__(128) f16 g_athi[MROWS * DD];
__device__ __align__(128) f16 g_atlo[MROWS * DD];
__device__ __align__(128) f16 g_ffhi[MROWS * FF];
__device__ __align__(128) f16 g_fflo[MROWS * FF];
__device__ __align__(128) f16 g_ixhi[MROWS * VV];
__device__ __align__(128) f16 g_ixlo[MROWS * VV];

// fp16 single-plane weights, transposed to [N,K]
#define OFF_TOK  0ull
#define OFF_QKV  2097152ull
#define OFF_PROJ 27262976ull
#define OFF_FF1  35651584ull
#define OFF_FF2  69206016ull
#define OFF_HEAD 102760448ull
#define W_TOTAL  104857600ull
__device__ __align__(128) f16 g_w[W_TOTAL];

// ---------------- small helpers ----------------
__device__ __forceinline__ uint32_t smem_u32(const void* p) {
    uint32_t a;
    asm("{ .reg .u64 t; cvta.to.shared.u64 t, %1; cvt.u32.u64 %0, t; }" : "=r"(a) : "l"(p));
    return a;
}
__device__ __forceinline__ void split_store(f16* hi, f16* lo, size_t idx, float v) {
    f16 h = __float2half(v);
    hi[idx] = h;
    lo[idx] = __float2half(v - __half2float(h));
}
__device__ __forceinline__ void ldsm4(uint32_t& r0, uint32_t& r1, uint32_t& r2, uint32_t& r3,
                                      uint32_t addr) {
    asm volatile("ldmatrix.sync.aligned.m8n8.x4.shared.b16 {%0,%1,%2,%3}, [%4];"
                 : "=r"(r0), "=r"(r1), "=r"(r2), "=r"(r3) : "r"(addr));
}
__device__ __forceinline__ void mma16816(float* d, const uint32_t* a, const uint32_t* b) {
    asm volatile(
        "mma.sync.aligned.m16n8k16.row.col.f32.f16.f16.f32 "
        "{%0,%1,%2,%3}, {%4,%5,%6,%7}, {%8,%9}, {%0,%1,%2,%3};"
        : "+f"(d[0]), "+f"(d[1]), "+f"(d[2]), "+f"(d[3])
        : "r"(a[0]), "r"(a[1]), "r"(a[2]), "r"(a[3]), "r"(b[0]), "r"(b[1]));
}
// packed fp32 helpers (Blackwell f32x2 — exact fp32, 2 MACs/issue; PTX-only)
__device__ __forceinline__ uint64_t pack2(float x, float y) {
    uint64_t r; asm("mov.b64 %0, {%1, %2};" : "=l"(r) : "f"(x), "f"(y)); return r;
}
__device__ __forceinline__ float2 unpack2(uint64_t v) {
    float2 f; asm("mov.b64 {%0, %1}, %2;" : "=f"(f.x), "=f"(f.y) : "l"(v)); return f;
}
__device__ __forceinline__ void ffma2(uint64_t& d, uint64_t a, uint64_t b) {
    asm("fma.rn.f32x2 %0, %1, %2, %0;" : "+l"(d) : "l"(a), "l"(b));
}
__device__ __forceinline__ void fmul2(uint64_t& d, uint64_t a) {
    asm("mul.rn.f32x2 %0, %0, %1;" : "+l"(d) : "l"(a));
}

// ---------------- weight prep: transpose + fp16 (single plane) ----------------
__global__ void tsplit_kernel(const float* __restrict__ src, f16* __restrict__ dst,
                              int K, int N, long sStride, long dStride) {
    int z = blockIdx.z;
    src += (size_t)z * sStride;
    dst += (size_t)z * dStride;
    __shared__ float t[32][33];
    int n0 = blockIdx.x * 32, k0 = blockIdx.y * 32;
    int tx = threadIdx.x, ty = threadIdx.y;
#pragma unroll
    for (int i = 0; i < 4; i++)
        t[ty + 8 * i][tx] = src[(size_t)(k0 + ty + 8 * i) * N + n0 + tx];
    __syncthreads();
#pragma unroll
    for (int i = 0; i < 4; i++) {
        int n = n0 + ty + 8 * i, k = k0 + tx;
        dst[(size_t)n * K + k] = __float2half(t[tx][ty + 8 * i]);
    }
}

// wq/wk/wv [L,H,D,DK] -> fused [3072,1024] per layer (transposed, fp16)
__global__ void tsplit_qkv(const float* __restrict__ wq, const float* __restrict__ wk,
                           const float* __restrict__ wv, f16* __restrict__ dst) {
    int z = blockIdx.z;                       // seg*L*H + l*H + h
    int seg = z / (LL * HH);
    int r = z % (LL * HH);
    int l = r / HH, h = r % HH;
    const float* src = (seg == 0 ? wq : seg == 1 ? wk : wv) + (size_t)(l * HH + h) * DD * DK;
    size_t dbase = (size_t)l * (3 * DD) * DD + (size_t)seg * DD * DD + (size_t)h * DK * DD;
    __shared__ float t[32][33];
    int n0 = blockIdx.x * 32, k0 = blockIdx.y * 32;
    int tx = threadIdx.x, ty = threadIdx.y;
#pragma unroll
    for (int i = 0; i < 4; i++)
        t[ty + 8 * i][tx] = src[(size_t)(k0 + ty + 8 * i) * DK + n0 + tx];
    __syncthreads();
#pragma unroll
    for (int i = 0; i < 4; i++) {
        int n = n0 + ty + 8 * i, k = k0 + tx;
        dst[dbase + (size_t)n * DD + k] = __float2half(t[tx][ty + 8 * i]);
    }
}

__global__ void prep_bqkv(const float* __restrict__ bq, const float* __restrict__ bk,
                          const float* __restrict__ bv, float* __restrict__ bt) {
    int idx = blockIdx.x * 256 + threadIdx.x;
    if (idx >= LL * 3 * DD) return;
    int c = idx % (3 * DD);
    int l = idx / (3 * DD);
    int seg = c >> 10;
    int hk = c & 1023;
    int h = hk >> 6, k = hk & 63;
    const float* src = (seg == 0) ? bq : (seg == 1 ? bk : bv);
    bt[idx] = src[(l * HH + h) * DK + k];
}

// elementwise fp32 -> hi/lo fp16 (for idx input)
__global__ void split_kernel(const float* __restrict__ src, f16* __restrict__ hi,
                             f16* __restrict__ lo, int n) {
    int i = blockIdx.x * 256 + threadIdx.x;
    if (i < n) split_store(hi, lo, i, src[i]);
}

// ---------------- LayerNorm: outputs fp16 hi/lo planes ----------------
__global__ void ln_kernel(const float* __restrict__ in, f16* __restrict__ ohi,
                          f16* __restrict__ olo, const float* __restrict__ g,
                          const float* __restrict__ b) {
    int row = blockIdx.x;
    int tid = threadIdx.x;
    const float* p = in + (size_t)row * DD;
    float v[4];
#pragma unroll
    for (int i = 0; i < 4; i++) v[i] = p[tid + i * 256];
    __shared__ float red[256];
    red[tid] = v[0] + v[1] + v[2] + v[3];
    __syncthreads();
#pragma unroll
    for (int off = 128; off > 0; off >>= 1) {
        if (tid < off) red[tid] += red[tid + off];
        __syncthreads();
    }
    float mean = red[0] * (1.0f / DD);
    __syncthreads();
    float s2 = 0.f;
#pragma unroll
    for (int i = 0; i < 4; i++) { float d = v[i] - mean; s2 += d * d; }
    red[tid] = s2;
    __syncthreads();
#pragma unroll
    for (int off = 128; off > 0; off >>= 1) {
        if (tid < off) red[tid] += red[tid + off];
        __syncthreads();
    }
    float r = rsqrtf(red[0] * (1.0f / DD) + 1e-5f);
#pragma unroll
    for (int i = 0; i < 4; i++) {
        int col = tid + i * 256;
        float val = (v[i] - mean) * r * g[col] + b[col];
        split_store(ohi, olo, (size_t)row * DD + col, val);
    }
}

// ---------------- split-fp16 HMMA GEMM (2-pass, fp32 accum — R11 proven) -------------
// C[M,N] = A[M,K] * W[K,N]; A as fp16 hi/lo planes [M,K], W single fp16 plane [N,K].
// acc = Ahi*B + Alo*B in fp32 registers.
// Block tile 128x128, BK=32, 256 threads, 8 warps of 64x32.
// 3-stage cp.async pipeline, one __syncthreads per K-chunk. Stage = 24KB.
// (R12 lesson: f16-accum HMMA is NOT faster on sm_103a — pipe is rate-identical.)
// EPI: 0 = fp32 +bias ; 1 = fp32 +bias+pos ; 2 = fp32 +bias+extra ; 3 = fp16 relu split
#define STG 24576
#define SMEM_MM (3 * STG)

template <int EPI>
__global__ __launch_bounds__(256) void mm_kernel(
    const f16* __restrict__ Ahi, const f16* __restrict__ Alo,
    const f16* __restrict__ Bw,
    float* __restrict__ C, const float* __restrict__ bias,
    const float* __restrict__ extra, f16* __restrict__ Ohi, f16* __restrict__ Olo,
    int N, int K) {
    extern __shared__ __align__(128) char smem[];
    uint32_t sb = smem_u32(smem);
    int tid = threadIdx.x, lane = tid & 31, wid = tid >> 5;
    int wm = wid >> 2, wn = wid & 3;            // warp grid 2x4, warp tile 64x32
    const int mBase = blockIdx.y * 128, nBase = blockIdx.x * 128;
    const f16* srcs[3] = { Ahi + (size_t)mBase * K, Alo + (size_t)mBase * K,
                           Bw + (size_t)nBase * K };
    const int NC = K >> 5;

    float acc[4][4][4];
#pragma unroll
    for (int i = 0; i < 4; i++)
#pragma unroll
        for (int j = 0; j < 4; j++)
#pragma unroll
            for (int c = 0; c < 4; c++) acc[i][j][c] = 0.f;

    int rowh = tid >> 2;     // 0..63
    int ch = tid & 3;        // 16B chunk within 64B row

    auto issue = [&](int c, int s) {
#pragma unroll
        for (int p = 0; p < 3; p++) {
#pragma unroll
            for (int w = 0; w < 2; w++) {
                int row = rowh + w * 64;
                int cc = ch ^ ((row >> 1) & 3);
                uint32_t d = sb + s * STG + p * 8192 + row * 64 + cc * 16;
                const f16* g = srcs[p] + (size_t)row * K + c * 32 + ch * 8;
                asm volatile("cp.async.cg.shared.global [%0], [%1], 16;"
                             :: "r"(d), "l"(g) : "memory");
            }
        }
        asm volatile("cp.async.commit_group;" ::: "memory");
    };

    // per-lane ldmatrix constants
    int mrl = ((lane >> 3) & 1) * 8 + (lane & 7);   // A: local m row
    int kha = (lane >> 4) & 1;                      // A: k half
    int nrl = ((lane >> 4) & 1) * 8 + (lane & 7);   // B: local n row
    int khb = (lane >> 3) & 1;                      // B: k half
    uint32_t aRow[4], aSw[4], bRow[2], bSw[2];
#pragma unroll
    for (int mt = 0; mt < 4; mt++) {
        int row = wm * 64 + mt * 16 + mrl;
        aRow[mt] = row * 64;
        aSw[mt] = (row >> 1) & 3;
    }
#pragma unroll
    for (int p2 = 0; p2 < 2; p2++) {
        int row = wn * 32 + p2 * 16 + nrl;
        bRow[p2] = row * 64;
        bSw[p2] = (row >> 1) & 3;
    }

    issue(0, 0);
    if (NC > 1) issue(1, 1);

    for (int r = 0; r < NC; r++) {
        if (r + 1 < NC) {
            asm volatile("cp.async.wait_group 1;" ::: "memory");
        } else {
            asm volatile("cp.async.wait_group 0;" ::: "memory");
        }
        __syncthreads();   // publishes chunk r AND guards stage (r-1) reuse
        if (r + 2 < NC) issue(r + 2, (r + 2) % 3);
        uint32_t stage = sb + (r % 3) * STG;
#pragma unroll
        for (int pass = 0; pass < 2; pass++) {
            uint32_t aOff = stage + (pass == 1 ? 8192 : 0);   // Ahi / Alo
            uint32_t bOff = stage + 16384;                    // B (shared by both passes)
#pragma unroll
            for (int ks = 0; ks < 2; ks++) {
                uint32_t a[4][4];
#pragma unroll
                for (int mt = 0; mt < 4; mt++) {
                    uint32_t cc = (uint32_t)(ks * 2 + kha) ^ aSw[mt];
                    ldsm4(a[mt][0], a[mt][1], a[mt][2], a[mt][3],
                          aOff + aRow[mt] + cc * 16);
                }
                uint32_t bb[8];
#pragma unroll
                for (int p2 = 0; p2 < 2; p2++) {
                    uint32_t cc = (uint32_t)(ks * 2 + khb) ^ bSw[p2];
                    ldsm4(bb[p2 * 4], bb[p2 * 4 + 1], bb[p2 * 4 + 2], bb[p2 * 4 + 3],
                          bOff + bRow[p2] + cc * 16);
                }
#pragma unroll
                for (int mt = 0; mt < 4; mt++)
#pragma unroll
                    for (int nt = 0; nt < 4; nt++)
                        mma16816(acc[mt][nt], a[mt], &bb[nt * 2]);
            }
        }
    }

    // epilogue: direct global writes
#pragma unroll
    for (int mt = 0; mt < 4; mt++) {
#pragma unroll
        for (int nt = 0; nt < 4; nt++) {
            int m0 = mBase + wm * 64 + mt * 16 + (lane >> 2);
            int n0 = nBase + wn * 32 + nt * 8 + (lane & 3) * 2;
            float b0 = bias[n0], b1 = bias[n0 + 1];
            float v00 = acc[mt][nt][0] + b0, v01 = acc[mt][nt][1] + b1;
            float v10 = acc[mt][nt][2] + b0, v11 = acc[mt][nt][3] + b1;
            int m1 = m0 + 8;
            if (EPI == 1) {
                v00 += extra[(size_t)(m0 & (TT - 1)) * N + n0];
                v01 += extra[(size_t)(m0 & (TT - 1)) * N + n0 + 1];
                v10 += extra[(size_t)(m1 & (TT - 1)) * N + n0];
                v11 += extra[(size_t)(m1 & (TT - 1)) * N + n0 + 1];
            }
            if (EPI == 2) {
                v00 += extra[(size_t)m0 * N + n0];
                v01 += extra[(size_t)m0 * N + n0 + 1];
                v10 += extra[(size_t)m1 * N + n0];
                v11 += extra[(size_t)m1 * N + n0 + 1];
            }
            if (EPI == 3) {
                v00 = fmaxf(v00, 0.f); v01 = fmaxf(v01, 0.f);
                v10 = fmaxf(v10, 0.f); v11 = fmaxf(v11, 0.f);
                split_store(Ohi, Olo, (size_t)m0 * N + n0, v00);
                split_store(Ohi, Olo, (size_t)m0 * N + n0 + 1, v01);
                split_store(Ohi, Olo, (size_t)m1 * N + n0, v10);
                split_store(Ohi, Olo, (size_t)m1 * N + n0 + 1, v11);
            } else {
                float2 lo2 = { v00, v01 };
                float2 hi2 = { v10, v11 };
                *(float2*)&C[(size_t)m0 * N + n0] = lo2;
                *(float2*)&C[(size_t)m1 * N + n0] = hi2;
            }
        }
    }
}

// ---------------- fused causal attention (flash-style, f32x2 packed math) ------------
// Exact fp32 numerics; fma.rn.f32x2 does 2 MACs/issue (ptxas never emits it from C++).
__global__ __launch_bounds__(64) void attn_kernel(const float* __restrict__ qkv,
                                                  f16* __restrict__ ohi,
                                                  f16* __restrict__ olo) {
    __shared__ float buf[64 * 64];
    __shared__ float Sc[64 * 65];
    int tid = threadIdx.x;
    int t0 = blockIdx.x * 64;
    int h = blockIdx.y;
    int b = blockIdx.z;
    int t = t0 + tid;

    const float4* qrow = (const float4*)(qkv + (size_t)(b * TT + t) * (3 * DD) + h * DK);
    uint64_t q2[32], o2[32];
#pragma unroll
    for (int i = 0; i < 16; i++) {
        float4 v = qrow[i];
        q2[i * 2]     = pack2(v.x, v.y);
        q2[i * 2 + 1] = pack2(v.z, v.w);
    }
    {
        uint64_t z = pack2(0.f, 0.f);
#pragma unroll
        for (int j = 0; j < 32; j++) o2[j] = z;
    }
    float mrow = -1e30f, lrow = 0.f;
    const uint64_t* buf2 = (const uint64_t*)buf;

    for (int s0 = 0; s0 <= t0; s0 += 64) {
        __syncthreads();
        {
            const float4* kb = (const float4*)(qkv + (size_t)(b * TT + s0 + tid) * (3 * DD)
                                               + DD + h * DK);
            float4* dst = (float4*)&buf[tid * 64];
#pragma unroll
            for (int i = 0; i < 16; i++) dst[i] = kb[i];
        }
        __syncthreads();
        float tmax = -1e30f;
        bool diag = (s0 == t0);
        for (int s = 0; s < 64; s++) {
            uint64_t acc2 = pack2(0.f, 0.f);
#pragma unroll
            for (int j = 0; j < 32; j++) ffma2(acc2, q2[j], buf2[s * 32 + j]);
            float2 av = unpack2(acc2);
            float acc = (av.x + av.y) * 0.125f;
            if (diag && s > tid) acc = -1e30f;
            Sc[tid * 65 + s] = acc;
            tmax = fmaxf(tmax, acc);
        }
        __syncthreads();
        {
            const float4* vb = (const float4*)(qkv + (size_t)(b * TT + s0 + tid) * (3 * DD)
                                               + 2 * DD + h * DK);
            float4* dst = (float4*)&buf[tid * 64];
#pragma unroll
            for (int i = 0; i < 16; i++) dst[i] = vb[i];
        }
        __syncthreads();
        float mnew = fmaxf(mrow, tmax);
        float corr = __expf(mrow - mnew);
        lrow *= corr;
        {
            uint64_t c2 = pack2(corr, corr);
#pragma unroll
            for (int j = 0; j < 32; j++) fmul2(o2[j], c2);
        }
        for (int s = 0; s < 64; s++) {
            float p = __expf(Sc[tid * 65 + s] - mnew);
            lrow += p;
            uint64_t p2 = pack2(p, p);
#pragma unroll
            for (int j = 0; j < 32; j++) ffma2(o2[j], p2, buf2[s * 32 + j]);
        }
        mrow = mnew;
    }
    float inv = 1.f / lrow;
    size_t obase = (size_t)(b * TT + t) * DD + h * DK;
#pragma unroll
    for (int j = 0; j < 32; j++) {
        float2 ov = unpack2(o2[j]);
        split_store(ohi, olo, obase + j * 2,     ov.x * inv);
        split_store(ohi, olo, obase + j * 2 + 1, ov.y * inv);
    }
}

// ---------------- host orchestration ----------------
extern "C" void kernel_launch(void* const* d_in, const int* in_sizes, int n_in,
                              void* d_out, int out_size) {
    const float* idx    = (const float*)d_in[0];
    const float* tok_w  = (const float*)d_in[1];
    const float* tok_b  = (const float*)d_in[2];
    const float* pos    = (const float*)d_in[3];
    const float* ln1_g  = (const float*)d_in[4];
    const float* ln1_b  = (const float*)d_in[5];
    const float* wq     = (const float*)d_in[6];
    const float* wk     = (const float*)d_in[7];
    const float* wv     = (const float*)d_in[8];
    const float* bq     = (const float*)d_in[9];
    const float* bk     = (const float*)d_in[10];
    const float* bv     = (const float*)d_in[11];
    const float* proj_w = (const float*)d_in[12];
    const float* proj_b = (const float*)d_in[13];
    const float* ln2_g  = (const float*)d_in[14];
    const float* ln2_b  = (const float*)d_in[15];
    const float* ff1_w  = (const float*)d_in[16];
    const float* ff1_b  = (const float*)d_in[17];
    const float* ff2_w  = (const float*)d_in[18];
    const float* ff2_b  = (const float*)d_in[19];
    const float* lnf_g  = (const float*)d_in[20];
    const float* lnf_b  = (const float*)d_in[21];
    const float* head_w = (const float*)d_in[22];
    const float* head_b = (const float*)d_in[23];
    float* out = (float*)d_out;

    float *x, *qkv, *bqkv;
    f16 *hhi, *hlo, *athi, *atlo, *ffhi, *fflo, *ixhi, *ixlo, *w;
    cudaGetSymbolAddress((void**)&x, g_x);
    cudaGetSymbolAddress((void**)&qkv, g_qkv);
    cudaGetSymbolAddress((void**)&bqkv, g_bqkv);
    cudaGetSymbolAddress((void**)&hhi, g_hhi);
    cudaGetSymbolAddress((void**)&hlo, g_hlo);
    cudaGetSymbolAddress((void**)&athi, g_athi);
    cudaGetSymbolAddress((void**)&atlo, g_atlo);
    cudaGetSymbolAddress((void**)&ffhi, g_ffhi);
    cudaGetSymbolAddress((void**)&fflo, g_fflo);
    cudaGetSymbolAddress((void**)&ixhi, g_ixhi);
    cudaGetSymbolAddress((void**)&ixlo, g_ixlo);
    cudaGetSymbolAddress((void**)&w, g_w);

    cudaFuncSetAttribute(mm_kernel<0>, cudaFuncAttributeMaxDynamicSharedMemorySize, SMEM_MM);
    cudaFuncSetAttribute(mm_kernel<1>, cudaFuncAttributeMaxDynamicSharedMemorySize, SMEM_MM);
    cudaFuncSetAttribute(mm_kernel<2>, cudaFuncAttributeMaxDynamicSharedMemorySize, SMEM_MM);
    cudaFuncSetAttribute(mm_kernel<3>, cudaFuncAttributeMaxDynamicSharedMemorySize, SMEM_MM);

    dim3 tb(32, 8);
    // weight prep: transpose + fp16 convert (single plane)
    tsplit_kernel<<<dim3(32, 64, 1), tb>>>(tok_w, w + OFF_TOK, 2048, 1024, 0, 0);
    tsplit_qkv<<<dim3(2, 32, 3 * LL * HH), tb>>>(wq, wk, wv, w + OFF_QKV);
    prep_bqkv<<<(LL * 3 * DD + 255) / 256, 256>>>(bq, bk, bv, bqkv);
    tsplit_kernel<<<dim3(32, 32, LL), tb>>>(proj_w, w + OFF_PROJ, 1024, 1024,
                                            1048576, 1048576);
    tsplit_kernel<<<dim3(128, 32, LL), tb>>>(ff1_w, w + OFF_FF1, 1024, 4096,
                                             4194304, 4194304);
    tsplit_kernel<<<dim3(32, 128, LL), tb>>>(ff2_w, w + OFF_FF2, 4096, 1024,
                                             4194304, 4194304);
    tsplit_kernel<<<dim3(64, 32, 1), tb>>>(head_w, w + OFF_HEAD, 1024, 2048, 0, 0);
    split_kernel<<<(MROWS * VV + 255) / 256, 256>>>(idx, ixhi, ixlo, MROWS * VV);

    // embedding: x = idx @ tok_w + tok_b + pos
    mm_kernel<1><<<dim3(8, 16), 256, SMEM_MM>>>(
        ixhi, ixlo, w + OFF_TOK, x, tok_b, pos, nullptr, nullptr, DD, VV);

    for (int l = 0; l < LL; l++) {
        ln_kernel<<<MROWS, 256>>>(x, hhi, hlo, ln1_g + l * DD, ln1_b + l * DD);
        mm_kernel<0><<<dim3(24, 16), 256, SMEM_MM>>>(
            hhi, hlo, w + OFF_QKV + (size_t)l * 3145728,
            qkv, bqkv + l * 3 * DD, nullptr, nullptr, nullptr, 3 * DD, DD);
        attn_kernel<<<dim3(TT / 64, HH, BB), 64>>>(qkv, athi, atlo);
        mm_kernel<2><<<dim3(8, 16), 256, SMEM_MM>>>(
            athi, atlo, w + OFF_PROJ + (size_t)l * 1048576,
            x, proj_b + l * DD, x, nullptr, nullptr, DD, DD);
        ln_kernel<<<MROWS, 256>>>(x, hhi, hlo, ln2_g + l * DD, ln2_b + l * DD);
        mm_kernel<3><<<dim3(32, 16), 256, SMEM_MM>>>(
            hhi, hlo, w + OFF_FF1 + (size_t)l * 4194304,
            nullptr, ff1_b + l * FF, nullptr, ffhi, fflo, FF, DD);
        mm_kernel<2><<<dim3(8, 16), 256, SMEM_MM>>>(
            ffhi, fflo, w + OFF_FF2 + (size_t)l * 4194304,
            x, ff2_b + l * DD, x, nullptr, nullptr, DD, FF);
    }

    ln_kernel<<<MROWS, 256>>>(x, hhi, hlo, lnf_g, lnf_b);
    mm_kernel<0><<<dim3(16, 16), 256, SMEM_MM>>>(
        hhi, hlo, w + OFF_HEAD, out, head_b, nullptr, nullptr, nullptr, VV, DD);
}

// round 15
// speedup vs baseline: 1.4283x; 1.2809x over previous
#include <cuda_runtime.h>
#include <cuda_bf16.h>
#include <cuda_fp16.h>
#include <cstdint>

// Problem dims
#define BB 2
#define TT 1024
#define VV 2048
#define DD 1024
#define HH 16
#define LL 8
#define DK 64
#define FF 4096
#define MROWS (BB*TT)   // 2048

typedef __half f16;

// ---------------- static scratch (no allocations allowed) ----------------
__device__ float g_x   [MROWS * DD];        // residual stream (fp32)
__device__ float g_qkv [MROWS * 3 * DD];    // fused qkv activations (fp32)
__device__ float g_bqkv[LL * 3 * DD];       // fused qkv bias

// fp16 single-plane activations
__device__ __align__(128) f16 g_h  [MROWS * DD];
__device__ __align__(128) f16 g_at [MROWS * DD];
__device__ __align__(128) f16 g_ff [MROWS * FF];
__device__ __align__(128) f16 g_ix [MROWS * VV];

// fp16 single-plane weights, transposed to [N,K]
#define OFF_TOK  0ull
#define OFF_QKV  2097152ull
#define OFF_PROJ 27262976ull
#define OFF_FF1  35651584ull
#define OFF_FF2  69206016ull
#define OFF_HEAD 102760448ull
#define W_TOTAL  104857600ull
__device__ __align__(128) f16 g_w[W_TOTAL];

// ---------------- small helpers ----------------
__device__ __forceinline__ uint32_t smem_u32(const void* p) {
    uint32_t a;
    asm("{ .reg .u64 t; cvta.to.shared.u64 t, %1; cvt.u32.u64 %0, t; }" : "=r"(a) : "l"(p));
    return a;
}
__device__ __forceinline__ void ldsm4(uint32_t& r0, uint32_t& r1, uint32_t& r2, uint32_t& r3,
                                      uint32_t addr) {
    asm volatile("ldmatrix.sync.aligned.m8n8.x4.shared.b16 {%0,%1,%2,%3}, [%4];"
                 : "=r"(r0), "=r"(r1), "=r"(r2), "=r"(r3) : "r"(addr));
}
__device__ __forceinline__ void mma16816(float* d, const uint32_t* a, const uint32_t* b) {
    asm volatile(
        "mma.sync.aligned.m16n8k16.row.col.f32.f16.f16.f32 "
        "{%0,%1,%2,%3}, {%4,%5,%6,%7}, {%8,%9}, {%0,%1,%2,%3};"
        : "+f"(d[0]), "+f"(d[1]), "+f"(d[2]), "+f"(d[3])
        : "r"(a[0]), "r"(a[1]), "r"(a[2]), "r"(a[3]), "r"(b[0]), "r"(b[1]));
}
// packed fp32 helpers (Blackwell f32x2 — exact fp32, 2 MACs/issue; PTX-only)
__device__ __forceinline__ uint64_t pack2(float x, float y) {
    uint64_t r; asm("mov.b64 %0, {%1, %2};" : "=l"(r) : "f"(x), "f"(y)); return r;
}
__device__ __forceinline__ float2 unpack2(uint64_t v) {
    float2 f; asm("mov.b64 {%0, %1}, %2;" : "=f"(f.x), "=f"(f.y) : "l"(v)); return f;
}
__device__ __forceinline__ void ffma2(uint64_t& d, uint64_t a, uint64_t b) {
    asm("fma.rn.f32x2 %0, %1, %2, %0;" : "+l"(d) : "l"(a), "l"(b));
}
__device__ __forceinline__ void fmul2(uint64_t& d, uint64_t a) {
    asm("mul.rn.f32x2 %0, %0, %1;" : "+l"(d) : "l"(a));
}

// ---------------- weight prep: transpose + fp16 (single plane) ----------------
__global__ void tsplit_kernel(const float* __restrict__ src, f16* __restrict__ dst,
                              int K, int N, long sStride, long dStride) {
    int z = blockIdx.z;
    src += (size_t)z * sStride;
    dst += (size_t)z * dStride;
    __shared__ float t[32][33];
    int n0 = blockIdx.x * 32, k0 = blockIdx.y * 32;
    int tx = threadIdx.x, ty = threadIdx.y;
#pragma unroll
    for (int i = 0; i < 4; i++)
        t[ty + 8 * i][tx] = src[(size_t)(k0 + ty + 8 * i) * N + n0 + tx];
    __syncthreads();
#pragma unroll
    for (int i = 0; i < 4; i++) {
        int n = n0 + ty + 8 * i, k = k0 + tx;
        dst[(size_t)n * K + k] = __float2half(t[tx][ty + 8 * i]);
    }
}

// wq/wk/wv [L,H,D,DK] -> fused [3072,1024] per layer (transposed, fp16)
__global__ void tsplit_qkv(const float* __restrict__ wq, const float* __restrict__ wk,
                           const float* __restrict__ wv, f16* __restrict__ dst) {
    int z = blockIdx.z;                       // seg*L*H + l*H + h
    int seg = z / (LL * HH);
    int r = z % (LL * HH);
    int l = r / HH, h = r % HH;
    const float* src = (seg == 0 ? wq : seg == 1 ? wk : wv) + (size_t)(l * HH + h) * DD * DK;
    size_t dbase = (size_t)l * (3 * DD) * DD + (size_t)seg * DD * DD + (size_t)h * DK * DD;
    __shared__ float t[32][33];
    int n0 = blockIdx.x * 32, k0 = blockIdx.y * 32;
    int tx = threadIdx.x, ty = threadIdx.y;
#pragma unroll
    for (int i = 0; i < 4; i++)
        t[ty + 8 * i][tx] = src[(size_t)(k0 + ty + 8 * i) * DK + n0 + tx];
    __syncthreads();
#pragma unroll
    for (int i = 0; i < 4; i++) {
        int n = n0 + ty + 8 * i, k = k0 + tx;
        dst[dbase + (size_t)n * DD + k] = __float2half(t[tx][ty + 8 * i]);
    }
}

__global__ void prep_bqkv(const float* __restrict__ bq, const float* __restrict__ bk,
                          const float* __restrict__ bv, float* __restrict__ bt) {
    int idx = blockIdx.x * 256 + threadIdx.x;
    if (idx >= LL * 3 * DD) return;
    int c = idx % (3 * DD);
    int l = idx / (3 * DD);
    int seg = c >> 10;
    int hk = c & 1023;
    int h = hk >> 6, k = hk & 63;
    const float* src = (seg == 0) ? bq : (seg == 1 ? bk : bv);
    bt[idx] = src[(l * HH + h) * DK + k];
}

// elementwise fp32 -> fp16 (for idx input)
__global__ void split_kernel(const float* __restrict__ src, f16* __restrict__ dst, int n) {
    int i = blockIdx.x * 256 + threadIdx.x;
    if (i < n) dst[i] = __float2half(src[i]);
}

// ---------------- LayerNorm: outputs fp16 single plane ----------------
__global__ void ln_kernel(const float* __restrict__ in, f16* __restrict__ outp,
                          const float* __restrict__ g, const float* __restrict__ b) {
    int row = blockIdx.x;
    int tid = threadIdx.x;
    const float* p = in + (size_t)row * DD;
    float v[4];
#pragma unroll
    for (int i = 0; i < 4; i++) v[i] = p[tid + i * 256];
    __shared__ float red[256];
    red[tid] = v[0] + v[1] + v[2] + v[3];
    __syncthreads();
#pragma unroll
    for (int off = 128; off > 0; off >>= 1) {
        if (tid < off) red[tid] += red[tid + off];
        __syncthreads();
    }
    float mean = red[0] * (1.0f / DD);
    __syncthreads();
    float s2 = 0.f;
#pragma unroll
    for (int i = 0; i < 4; i++) { float d = v[i] - mean; s2 += d * d; }
    red[tid] = s2;
    __syncthreads();
#pragma unroll
    for (int off = 128; off > 0; off >>= 1) {
        if (tid < off) red[tid] += red[tid + off];
        __syncthreads();
    }
    float r = rsqrtf(red[0] * (1.0f / DD) + 1e-5f);
#pragma unroll
    for (int i = 0; i < 4; i++) {
        int col = tid + i * 256;
        float val = (v[i] - mean) * r * g[col] + b[col];
        outp[(size_t)row * DD + col] = __float2half(val);
    }
}

// ---------------- fp16 HMMA GEMM (single pass) ----------------
// C[M,N] = A[M,K] * W[K,N]; A fp16 [M,K], W fp16 [N,K]; fp32 accumulate.
// Block tile 128x128, BK=32, 256 threads, 8 warps of 64x32 (proven shape).
// 3-stage cp.async pipeline, one __syncthreads per K-chunk. Stage = 16KB.
// Error budget: A-rounding (2^-12) + W-rounding (2^-12) in quadrature ->
// predicted final rel_err ~6.5e-4 < 1e-3 (calibrated on R11/R4 measurements).
// EPI: 0 = fp32 +bias ; 1 = fp32 +bias+pos ; 2 = fp32 +bias+extra ; 3 = fp16 relu
#define STG 16384
#define SMEM_MM (3 * STG)

template <int EPI>
__global__ __launch_bounds__(256) void mm_kernel(
    const f16* __restrict__ A, const f16* __restrict__ Bw,
    float* __restrict__ C, const float* __restrict__ bias,
    const float* __restrict__ extra, f16* __restrict__ Of16,
    int N, int K) {
    extern __shared__ __align__(128) char smem[];
    uint32_t sb = smem_u32(smem);
    int tid = threadIdx.x, lane = tid & 31, wid = tid >> 5;
    int wm = wid >> 2, wn = wid & 3;            // warp grid 2x4, warp tile 64x32
    const int mBase = blockIdx.y * 128, nBase = blockIdx.x * 128;
    const f16* srcs[2] = { A + (size_t)mBase * K, Bw + (size_t)nBase * K };
    const int NC = K >> 5;

    float acc[4][4][4];
#pragma unroll
    for (int i = 0; i < 4; i++)
#pragma unroll
        for (int j = 0; j < 4; j++)
#pragma unroll
            for (int c = 0; c < 4; c++) acc[i][j][c] = 0.f;

    int rowh = tid >> 2;     // 0..63
    int ch = tid & 3;        // 16B chunk within 64B row

    auto issue = [&](int c, int s) {
#pragma unroll
        for (int p = 0; p < 2; p++) {
#pragma unroll
            for (int w = 0; w < 2; w++) {
                int row = rowh + w * 64;
                int cc = ch ^ ((row >> 1) & 3);
                uint32_t d = sb + s * STG + p * 8192 + row * 64 + cc * 16;
                const f16* g = srcs[p] + (size_t)row * K + c * 32 + ch * 8;
                asm volatile("cp.async.cg.shared.global [%0], [%1], 16;"
                             :: "r"(d), "l"(g) : "memory");
            }
        }
        asm volatile("cp.async.commit_group;" ::: "memory");
    };

    // per-lane ldmatrix constants
    int mrl = ((lane >> 3) & 1) * 8 + (lane & 7);   // A: local m row
    int kha = (lane >> 4) & 1;                      // A: k half
    int nrl = ((lane >> 4) & 1) * 8 + (lane & 7);   // B: local n row
    int khb = (lane >> 3) & 1;                      // B: k half
    uint32_t aRow[4], aSw[4], bRow[2], bSw[2];
#pragma unroll
    for (int mt = 0; mt < 4; mt++) {
        int row = wm * 64 + mt * 16 + mrl;
        aRow[mt] = row * 64;
        aSw[mt] = (row >> 1) & 3;
    }
#pragma unroll
    for (int p2 = 0; p2 < 2; p2++) {
        int row = wn * 32 + p2 * 16 + nrl;
        bRow[p2] = row * 64;
        bSw[p2] = (row >> 1) & 3;
    }

    issue(0, 0);
    if (NC > 1) issue(1, 1);

    for (int r = 0; r < NC; r++) {
        if (r + 1 < NC) {
            asm volatile("cp.async.wait_group 1;" ::: "memory");
        } else {
            asm volatile("cp.async.wait_group 0;" ::: "memory");
        }
        __syncthreads();   // publishes chunk r AND guards stage (r-1) reuse
        if (r + 2 < NC) issue(r + 2, (r + 2) % 3);
        uint32_t stage = sb + (r % 3) * STG;
        uint32_t bOff = stage + 8192;
#pragma unroll
        for (int ks = 0; ks < 2; ks++) {
            uint32_t a[4][4];
#pragma unroll
            for (int mt = 0; mt < 4; mt++) {
                uint32_t cc = (uint32_t)(ks * 2 + kha) ^ aSw[mt];
                ldsm4(a[mt][0], a[mt][1], a[mt][2], a[mt][3],
                      stage + aRow[mt] + cc * 16);
            }
            uint32_t bb[8];
#pragma unroll
            for (int p2 = 0; p2 < 2; p2++) {
                uint32_t cc = (uint32_t)(ks * 2 + khb) ^ bSw[p2];
                ldsm4(bb[p2 * 4], bb[p2 * 4 + 1], bb[p2 * 4 + 2], bb[p2 * 4 + 3],
                      bOff + bRow[p2] + cc * 16);
            }
#pragma unroll
            for (int mt = 0; mt < 4; mt++)
#pragma unroll
                for (int nt = 0; nt < 4; nt++)
                    mma16816(acc[mt][nt], a[mt], &bb[nt * 2]);
        }
    }

    // epilogue: direct global writes
#pragma unroll
    for (int mt = 0; mt < 4; mt++) {
#pragma unroll
        for (int nt = 0; nt < 4; nt++) {
            int m0 = mBase + wm * 64 + mt * 16 + (lane >> 2);
            int n0 = nBase + wn * 32 + nt * 8 + (lane & 3) * 2;
            float b0 = bias[n0], b1 = bias[n0 + 1];
            float v00 = acc[mt][nt][0] + b0, v01 = acc[mt][nt][1] + b1;
            float v10 = acc[mt][nt][2] + b0, v11 = acc[mt][nt][3] + b1;
            int m1 = m0 + 8;
            if (EPI == 1) {
                v00 += extra[(size_t)(m0 & (TT - 1)) * N + n0];
                v01 += extra[(size_t)(m0 & (TT - 1)) * N + n0 + 1];
                v10 += extra[(size_t)(m1 & (TT - 1)) * N + n0];
                v11 += extra[(size_t)(m1 & (TT - 1)) * N + n0 + 1];
            }
            if (EPI == 2) {
                v00 += extra[(size_t)m0 * N + n0];
                v01 += extra[(size_t)m0 * N + n0 + 1];
                v10 += extra[(size_t)m1 * N + n0];
                v11 += extra[(size_t)m1 * N + n0 + 1];
            }
            if (EPI == 3) {
                __half2 h0 = __floats2half2_rn(fmaxf(v00, 0.f), fmaxf(v01, 0.f));
                __half2 h1 = __floats2half2_rn(fmaxf(v10, 0.f), fmaxf(v11, 0.f));
                *(__half2*)&Of16[(size_t)m0 * N + n0] = h0;
                *(__half2*)&Of16[(size_t)m1 * N + n0] = h1;
            } else {
                float2 lo2 = { v00, v01 };
                float2 hi2 = { v10, v11 };
                *(float2*)&C[(size_t)m0 * N + n0] = lo2;
                *(float2*)&C[(size_t)m1 * N + n0] = hi2;
            }
        }
    }
}

// ---------------- fused causal attention (flash-style, f32x2 packed math) ------------
__global__ __launch_bounds__(64) void attn_kernel(const float* __restrict__ qkv,
                                                  f16* __restrict__ outp) {
    __shared__ float buf[64 * 64];
    __shared__ float Sc[64 * 65];
    int tid = threadIdx.x;
    int t0 = blockIdx.x * 64;
    int h = blockIdx.y;
    int b = blockIdx.z;
    int t = t0 + tid;

    const float4* qrow = (const float4*)(qkv + (size_t)(b * TT + t) * (3 * DD) + h * DK);
    uint64_t q2[32], o2[32];
#pragma unroll
    for (int i = 0; i < 16; i++) {
        float4 v = qrow[i];
        q2[i * 2]     = pack2(v.x, v.y);
        q2[i * 2 + 1] = pack2(v.z, v.w);
    }
    {
        uint64_t z = pack2(0.f, 0.f);
#pragma unroll
        for (int j = 0; j < 32; j++) o2[j] = z;
    }
    float mrow = -1e30f, lrow = 0.f;
    const uint64_t* buf2 = (const uint64_t*)buf;

    for (int s0 = 0; s0 <= t0; s0 += 64) {
        __syncthreads();
        {
            const float4* kb = (const float4*)(qkv + (size_t)(b * TT + s0 + tid) * (3 * DD)
                                               + DD + h * DK);
            float4* dst = (float4*)&buf[tid * 64];
#pragma unroll
            for (int i = 0; i < 16; i++) dst[i] = kb[i];
        }
        __syncthreads();
        float tmax = -1e30f;
        bool diag = (s0 == t0);
        for (int s = 0; s < 64; s++) {
            uint64_t acc2 = pack2(0.f, 0.f);
#pragma unroll
            for (int j = 0; j < 32; j++) ffma2(acc2, q2[j], buf2[s * 32 + j]);
            float2 av = unpack2(acc2);
            float acc = (av.x + av.y) * 0.125f;
            if (diag && s > tid) acc = -1e30f;
            Sc[tid * 65 + s] = acc;
            tmax = fmaxf(tmax, acc);
        }
        __syncthreads();
        {
            const float4* vb = (const float4*)(qkv + (size_t)(b * TT + s0 + tid) * (3 * DD)
                                               + 2 * DD + h * DK);
            float4* dst = (float4*)&buf[tid * 64];
#pragma unroll
            for (int i = 0; i < 16; i++) dst[i] = vb[i];
        }
        __syncthreads();
        float mnew = fmaxf(mrow, tmax);
        float corr = __expf(mrow - mnew);
        lrow *= corr;
        {
            uint64_t c2 = pack2(corr, corr);
#pragma unroll
            for (int j = 0; j < 32; j++) fmul2(o2[j], c2);
        }
        for (int s = 0; s < 64; s++) {
            float p = __expf(Sc[tid * 65 + s] - mnew);
            lrow += p;
            uint64_t p2 = pack2(p, p);
#pragma unroll
            for (int j = 0; j < 32; j++) ffma2(o2[j], p2, buf2[s * 32 + j]);
        }
        mrow = mnew;
    }
    float inv = 1.f / lrow;
    size_t obase = (size_t)(b * TT + t) * DD + h * DK;
#pragma unroll
    for (int j = 0; j < 32; j++) {
        float2 ov = unpack2(o2[j]);
        *(__half2*)&outp[obase + j * 2] = __floats2half2_rn(ov.x * inv, ov.y * inv);
    }
}

// ---------------- host orchestration ----------------
extern "C" void kernel_launch(void* const* d_in, const int* in_sizes, int n_in,
                              void* d_out, int out_size) {
    const float* idx    = (const float*)d_in[0];
    const float* tok_w  = (const float*)d_in[1];
    const float* tok_b  = (const float*)d_in[2];
    const float* pos    = (const float*)d_in[3];
    const float* ln1_g  = (const float*)d_in[4];
    const float* ln1_b  = (const float*)d_in[5];
    const float* wq     = (const float*)d_in[6];
    const float* wk     = (const float*)d_in[7];
    const float* wv     = (const float*)d_in[8];
    const float* bq     = (const float*)d_in[9];
    const float* bk     = (const float*)d_in[10];
    const float* bv     = (const float*)d_in[11];
    const float* proj_w = (const float*)d_in[12];
    const float* proj_b = (const float*)d_in[13];
    const float* ln2_g  = (const float*)d_in[14];
    const float* ln2_b  = (const float*)d_in[15];
    const float* ff1_w  = (const float*)d_in[16];
    const float* ff1_b  = (const float*)d_in[17];
    const float* ff2_w  = (const float*)d_in[18];
    const float* ff2_b  = (const float*)d_in[19];
    const float* lnf_g  = (const float*)d_in[20];
    const float* lnf_b  = (const float*)d_in[21];
    const float* head_w = (const float*)d_in[22];
    const float* head_b = (const float*)d_in[23];
    float* out = (float*)d_out;

    float *x, *qkv, *bqkv;
    f16 *hbuf, *at, *ff, *ix, *w;
    cudaGetSymbolAddress((void**)&x, g_x);
    cudaGetSymbolAddress((void**)&qkv, g_qkv);
    cudaGetSymbolAddress((void**)&bqkv, g_bqkv);
    cudaGetSymbolAddress((void**)&hbuf, g_h);
    cudaGetSymbolAddress((void**)&at, g_at);
    cudaGetSymbolAddress((void**)&ff, g_ff);
    cudaGetSymbolAddress((void**)&ix, g_ix);
    cudaGetSymbolAddress((void**)&w, g_w);

    cudaFuncSetAttribute(mm_kernel<0>, cudaFuncAttributeMaxDynamicSharedMemorySize, SMEM_MM);
    cudaFuncSetAttribute(mm_kernel<1>, cudaFuncAttributeMaxDynamicSharedMemorySize, SMEM_MM);
    cudaFuncSetAttribute(mm_kernel<2>, cudaFuncAttributeMaxDynamicSharedMemorySize, SMEM_MM);
    cudaFuncSetAttribute(mm_kernel<3>, cudaFuncAttributeMaxDynamicSharedMemorySize, SMEM_MM);

    dim3 tb(32, 8);
    // weight prep: transpose + fp16 convert (single plane)
    tsplit_kernel<<<dim3(32, 64, 1), tb>>>(tok_w, w + OFF_TOK, 2048, 1024, 0, 0);
    tsplit_qkv<<<dim3(2, 32, 3 * LL * HH), tb>>>(wq, wk, wv, w + OFF_QKV);
    prep_bqkv<<<(LL * 3 * DD + 255) / 256, 256>>>(bq, bk, bv, bqkv);
    tsplit_kernel<<<dim3(32, 32, LL), tb>>>(proj_w, w + OFF_PROJ, 1024, 1024,
                                            1048576, 1048576);
    tsplit_kernel<<<dim3(128, 32, LL), tb>>>(ff1_w, w + OFF_FF1, 1024, 4096,
                                             4194304, 4194304);
    tsplit_kernel<<<dim3(32, 128, LL), tb>>>(ff2_w, w + OFF_FF2, 4096, 1024,
                                             4194304, 4194304);
    tsplit_kernel<<<dim3(64, 32, 1), tb>>>(head_w, w + OFF_HEAD, 1024, 2048, 0, 0);
    split_kernel<<<(MROWS * VV + 255) / 256, 256>>>(idx, ix, MROWS * VV);

    // embedding: x = idx @ tok_w + tok_b + pos
    mm_kernel<1><<<dim3(8, 16), 256, SMEM_MM>>>(
        ix, w + OFF_TOK, x, tok_b, pos, nullptr, DD, VV);

    for (int l = 0; l < LL; l++) {
        ln_kernel<<<MROWS, 256>>>(x, hbuf, ln1_g + l * DD, ln1_b + l * DD);
        mm_kernel<0><<<dim3(24, 16), 256, SMEM_MM>>>(
            hbuf, w + OFF_QKV + (size_t)l * 3145728,
            qkv, bqkv + l * 3 * DD, nullptr, nullptr, 3 * DD, DD);
        attn_kernel<<<dim3(TT / 64, HH, BB), 64>>>(qkv, at);
        mm_kernel<2><<<dim3(8, 16), 256, SMEM_MM>>>(
            at, w + OFF_PROJ + (size_t)l * 1048576,
            x, proj_b + l * DD, x, nullptr, DD, DD);
        ln_kernel<<<MROWS, 256>>>(x, hbuf, ln2_g + l * DD, ln2_b + l * DD);
        mm_kernel<3><<<dim3(32, 16), 256, SMEM_MM>>>(
            hbuf, w + OFF_FF1 + (size_t)l * 4194304,
            nullptr, ff1_b + l * FF, nullptr, ff, FF, DD);
        mm_kernel<2><<<dim3(8, 16), 256, SMEM_MM>>>(
            ff, w + OFF_FF2 + (size_t)l * 4194304,
            x, ff2_b + l * DD, x, nullptr, DD, FF);
    }

    ln_kernel<<<MROWS, 256>>>(x, hbuf, lnf_g, lnf_b);
    mm_kernel<0><<<dim3(16, 16), 256, SMEM_MM>>>(
        hbuf, w + OFF_HEAD, out, head_b, nullptr, nullptr, VV, DD);
}